// round 15
// baseline (speedup 1.0000x reference)
#include <cuda_runtime.h>
#include <cuda_fp16.h>
#include <cstdint>

// Problem constants
#define NN 8192
#define HH 512
#define LL 3
#define OO 512
#define MAXNZ 256
#define LN_EPS 1e-5f

// fp16 GEMM tiling
#define HBK 64
#define HA_STRIDE 72
#define HA_BYTES (128 * HA_STRIDE * 2)
#define HSTAGE_BYTES (2 * HA_BYTES)
#define HSMEM_BYTES (2 * HSTAGE_BYTES)

// ---------------------------------------------------------------------------
// Scratch (device globals — no allocations allowed)
// ---------------------------------------------------------------------------
__device__ __half g_Xh[NN * HH];        // activations, fp16
__device__ __half g_Sh[NN * HH];        // fp16 intermediate (SpMM out / H0)
__device__ __half g_Zh[NN * HH];        // fp16 pre-LN (layers 1-2)
__device__ __half g_Wmt[LL * HH * HH];  // mlp_w transposed, half [n][j]
__device__ __half g_Wch[LL * HH * HH];  // conv_w as-is, half [k][j]
__device__ __half g_Wth[4 * HH * HH];   // W'^T (3) + lin_w^T (1), half [n][k]
__device__ float  g_bf[LL * HH];        // fused bias
__device__ int    g_colv[NN * MAXNZ];
__device__ float  g_valv[NN * MAXNZ];   // RAW adjacency weights (unscaled)
__device__ int    g_cnt[NN];
__device__ float  g_dinv[NN];

// ---------------------------------------------------------------------------
// Streams (module-load creation; serial fallback)
// ---------------------------------------------------------------------------
struct HxStreams {
    cudaStream_t s1 = nullptr, s2 = nullptr;
    cudaEvent_t  e0 = nullptr, e1 = nullptr, e2 = nullptr;
    bool ok = false;
    HxStreams() {
        ok = (cudaStreamCreateWithFlags(&s1, cudaStreamNonBlocking) == cudaSuccess) &&
             (cudaStreamCreateWithFlags(&s2, cudaStreamNonBlocking) == cudaSuccess) &&
             (cudaEventCreateWithFlags(&e0, cudaEventDisableTiming) == cudaSuccess) &&
             (cudaEventCreateWithFlags(&e1, cudaEventDisableTiming) == cudaSuccess) &&
             (cudaEventCreateWithFlags(&e2, cudaEventDisableTiming) == cudaSuccess);
    }
};
static HxStreams g_hx;

// ---------------------------------------------------------------------------
// Helpers
// ---------------------------------------------------------------------------
__device__ __forceinline__ void cp16(uint32_t smaddr, const void* gptr) {
    asm volatile("cp.async.cg.shared.global [%0], [%1], 16;" :: "r"(smaddr), "l"(gptr));
}
__device__ __forceinline__ void cp_commit() {
    asm volatile("cp.async.commit_group;");
}
template<int N_> __device__ __forceinline__ void cp_wait() {
    asm volatile("cp.async.wait_group %0;" :: "n"(N_));
}
__device__ __forceinline__ void ldsm_x4(uint32_t* r, uint32_t addr) {
    asm volatile("ldmatrix.sync.aligned.m8n8.x4.shared.b16 {%0,%1,%2,%3}, [%4];"
                 : "=r"(r[0]), "=r"(r[1]), "=r"(r[2]), "=r"(r[3]) : "r"(addr));
}

// ---------------------------------------------------------------------------
// dense adjacency -> CSR (raw weights) + dinv (deterministic order)
// ---------------------------------------------------------------------------
__global__ __launch_bounds__(256) void build_csr_kernel(const float* __restrict__ Aadj)
{
    const int i = blockIdx.x;
    const int t = threadIdx.x;

    __shared__ float s_red[256];
    __shared__ int   s_scan[256];
    __shared__ int   s_diag;
    if (t == 0) s_diag = 0;
    __syncthreads();

    const float* row = Aadj + (size_t)i * NN;
    const int j0 = t * 32;

    float lsum = 0.f;
    int   lcnt = 0;
    #pragma unroll
    for (int q = 0; q < 8; q++) {
        const float4 a = *(const float4*)&row[j0 + q * 4];
        const float vv[4] = {a.x, a.y, a.z, a.w};
        #pragma unroll
        for (int e = 0; e < 4; e++) {
            const int j = j0 + q * 4 + e;
            const float v = vv[e];
            if (v > 0.f) {
                lsum += v;
                lcnt++;
                if (j == i) s_diag = 1;
            }
        }
    }

    s_scan[t] = lcnt;
    s_red[t]  = lsum;
    __syncthreads();

    for (int st = 128; st > 0; st >>= 1) {
        if (t < st) s_red[t] += s_red[t + st];
        __syncthreads();
    }
    for (int st = 1; st < 256; st <<= 1) {
        int add = (t >= st) ? s_scan[t - st] : 0;
        __syncthreads();
        s_scan[t] += add;
        __syncthreads();
    }

    const int excl  = s_scan[t] - lcnt;
    const int total = s_scan[255];
    const int selfloop = (s_diag == 0);

    int off = excl;
    const int base = i * MAXNZ;
    #pragma unroll
    for (int q = 0; q < 8; q++) {
        const float4 a = *(const float4*)&row[j0 + q * 4];
        const float vv[4] = {a.x, a.y, a.z, a.w};
        #pragma unroll
        for (int e = 0; e < 4; e++) {
            const int j = j0 + q * 4 + e;
            const float v = vv[e];
            if (v > 0.f) {
                if (off < MAXNZ) {
                    g_colv[base + off] = j;
                    g_valv[base + off] = v;
                }
                off++;
            }
        }
    }

    if (t == 0) {
        int   c   = total;
        float deg = s_red[0];
        if (selfloop) {
            if (c < MAXNZ) {
                g_colv[base + c] = i;
                g_valv[base + c] = 1.f;
            }
            c++;
            deg += 1.f;
        }
        g_cnt[i]  = c < MAXNZ ? c : MAXNZ;
        g_dinv[i] = (deg > 0.f) ? rsqrtf(deg) : 0.f;
    }
}

// ---------------------------------------------------------------------------
// Merged prep (one launch): grid (16,16,23), block (32,32)
//   z 0..2  : transpose mlp_w[z] fp32 [k][n] -> fp16 g_Wmt[z] [n][k]
//   z 3     : transpose lin_w    fp32 [k][n] -> fp16 g_Wth slot 3 [n][k]
//   z 4..6  : f2h conv_w[z-4] -> g_Wch[z-4] (as-is layout)
//   z 7..22 : f2h node -> g_Xh (256 tiles of 1024 elems per z)
// ---------------------------------------------------------------------------
__global__ __launch_bounds__(1024) void prep_kernel(
    const float* __restrict__ mlp_w, const float* __restrict__ lin_w,
    const float* __restrict__ conv_w, const float* __restrict__ node)
{
    const int z = blockIdx.z;
    if (z < 4) {
        __shared__ float ts[32][33];
        const float* in = (z < 3) ? (mlp_w + (size_t)z * HH * HH) : lin_w;
        __half* out = (z < 3) ? (g_Wmt + (size_t)z * HH * HH)
                              : (g_Wth + (size_t)3 * HH * HH);
        const int k_in = blockIdx.y * 32 + threadIdx.y;
        const int n_in = blockIdx.x * 32 + threadIdx.x;
        ts[threadIdx.y][threadIdx.x] = in[(size_t)k_in * HH + n_in];
        __syncthreads();
        const int n_out = blockIdx.x * 32 + threadIdx.y;
        const int k_out = blockIdx.y * 32 + threadIdx.x;
        out[(size_t)n_out * HH + k_out] = __float2half_rn(ts[threadIdx.x][threadIdx.y]);
    } else if (z < 7) {
        const int m = z - 4;
        const int tile = blockIdx.y * 16 + blockIdx.x;
        const size_t off = (size_t)m * HH * HH
                         + (size_t)tile * 1024 + threadIdx.y * 32 + threadIdx.x;
        g_Wch[off] = __float2half_rn(conv_w[off]);
    } else {
        const int zt = z - 7;                                    // 0..15
        const int tile = zt * 256 + blockIdx.y * 16 + blockIdx.x;
        const size_t off = (size_t)tile * 1024 + threadIdx.y * 32 + threadIdx.x;
        g_Xh[off] = __float2half_rn(node[off]);
    }
}

// ---------------------------------------------------------------------------
// Fused bias (parallel, 96 blocks): bf[l][n] = conv_b[l] @ mlp_w[l] + mlp_b[l]
// grid (HH/16, LL), 256 thr = 16 k-groups x 16 n; deterministic asc-kg combine
// ---------------------------------------------------------------------------
__global__ __launch_bounds__(256) void bias_fuse_kernel(
    const float* __restrict__ conv_b, const float* __restrict__ mlp_w,
    const float* __restrict__ mlp_b)
{
    __shared__ float s[16][16];
    const int l  = blockIdx.y;
    const int n0 = blockIdx.x * 16;
    const int n  = threadIdx.x & 15;
    const int kg = threadIdx.x >> 4;
    const float* W  = mlp_w + (size_t)l * HH * HH;
    const float* cb = conv_b + l * HH;

    float acc = 0.f;
    const int kbase = kg * 32;
    #pragma unroll 8
    for (int k = 0; k < 32; k++)
        acc += cb[kbase + k] * W[(size_t)(kbase + k) * HH + n0 + n];
    s[kg][n] = acc;
    __syncthreads();
    if (kg == 0) {
        float r = mlp_b[l * HH + n0 + n];
        #pragma unroll
        for (int j = 0; j < 16; j++) r += s[j][n];
        g_bf[l * HH + n0 + n] = r;
    }
}

// ---------------------------------------------------------------------------
// fp16 tensor-core GEMM  C[M,N] = A[M,K] @ Bt[N,K]^T (+ bias), fp32 accum.
// OUT_HALF: write __half (bias still added if non-null). Batched over z.
// ---------------------------------------------------------------------------
template<bool OUT_HALF>
__global__ __launch_bounds__(256, 2) void hgemm_kernel(
    const __half* __restrict__ A, const __half* __restrict__ Bt,
    const float* __restrict__ bias, void* __restrict__ Cv,
    int M, int K, int N, size_t sa, size_t sb, size_t sc)
{
    extern __shared__ char smh[];
    const uint32_t smbase = (uint32_t)__cvta_generic_to_shared(smh);

    A  += (size_t)blockIdx.z * sa;
    Bt += (size_t)blockIdx.z * sb;
    const size_t coff = (size_t)blockIdx.z * sc;

    const int t    = threadIdx.x;
    const int warp = t >> 5;
    const int lane = t & 31;
    const int g    = lane >> 2;
    const int tg   = lane & 3;
    const int wm   = warp >> 2;
    const int wn   = warp & 3;
    const int m0   = blockIdx.y * 128;
    const int n0   = blockIdx.x * 128;

    const int sel = lane >> 3;
    const int lr  = lane & 7;
    const int arow  = lr + ((sel & 1) ? 8 : 0);
    const int akoff = (sel & 2) ? 8 : 0;
    const int brow  = lr + ((sel & 2) ? 8 : 0);
    const int bkoff = (sel & 1) ? 8 : 0;

    float acc[4][4][4];
    #pragma unroll
    for (int a = 0; a < 4; a++)
        #pragma unroll
        for (int b = 0; b < 4; b++)
            #pragma unroll
            for (int c = 0; c < 4; c++) acc[a][b][c] = 0.f;

    const int NT = K / HBK;

    auto load_stage = [&](int s, int k0) {
        const uint32_t sb_ = smbase + (uint32_t)s * HSTAGE_BYTES;
        #pragma unroll
        for (int i = 0; i < 4; i++) {
            const int id = t + i * 256;
            const int r  = id >> 3;
            const int c  = id & 7;
            const uint32_t so = (uint32_t)(r * (HA_STRIDE * 2) + c * 16);
            cp16(sb_ + so,            &A [(size_t)(m0 + r) * K + k0 + c * 8]);
            cp16(sb_ + HA_BYTES + so, &Bt[(size_t)(n0 + r) * K + k0 + c * 8]);
        }
    };

    load_stage(0, 0);
    cp_commit();

    for (int it = 0; it < NT; it++) {
        const int cur = it & 1;
        if (it + 1 < NT) {
            load_stage((it + 1) & 1, (it + 1) * HBK);
            cp_commit();
            cp_wait<1>();
        } else {
            cp_wait<0>();
        }
        __syncthreads();

        const uint32_t sA = smbase + (uint32_t)cur * HSTAGE_BYTES;
        const uint32_t sB = sA + HA_BYTES;

        #pragma unroll
        for (int ks = 0; ks < HBK; ks += 16) {
            uint32_t af[4][4];
            #pragma unroll
            for (int mi = 0; mi < 4; mi++) {
                const int r = wm * 64 + mi * 16 + arow;
                ldsm_x4(af[mi], sA + (uint32_t)(r * (HA_STRIDE * 2) + (ks + akoff) * 2));
            }
            uint32_t bfr[2][4];
            #pragma unroll
            for (int p = 0; p < 2; p++) {
                const int r = wn * 32 + p * 16 + brow;
                ldsm_x4(bfr[p], sB + (uint32_t)(r * (HA_STRIDE * 2) + (ks + bkoff) * 2));
            }
            #pragma unroll
            for (int mi = 0; mi < 4; mi++)
                #pragma unroll
                for (int ni = 0; ni < 4; ni++) {
                    const int p   = ni >> 1;
                    const int idx = (ni & 1) * 2;
                    asm volatile(
                        "mma.sync.aligned.m16n8k16.row.col.f32.f16.f16.f32 "
                        "{%0,%1,%2,%3}, {%4,%5,%6,%7}, {%8,%9}, {%0,%1,%2,%3};"
                        : "+f"(acc[mi][ni][0]), "+f"(acc[mi][ni][1]),
                          "+f"(acc[mi][ni][2]), "+f"(acc[mi][ni][3])
                        : "r"(af[mi][0]), "r"(af[mi][1]),
                          "r"(af[mi][2]), "r"(af[mi][3]),
                          "r"(bfr[p][idx]), "r"(bfr[p][idx + 1]));
                }
        }
        __syncthreads();
    }

    #pragma unroll
    for (int ni = 0; ni < 4; ni++) {
        const int col = n0 + wn * 32 + ni * 8 + 2 * tg;
        float b0 = 0.f, b1 = 0.f;
        if (bias) { b0 = bias[col]; b1 = bias[col + 1]; }
        #pragma unroll
        for (int mi = 0; mi < 4; mi++) {
            const int r0 = m0 + wm * 64 + mi * 16 + g;
            if (OUT_HALF) {
                __half* C = (__half*)Cv + coff;
                __half2 h0 = __floats2half2_rn(acc[mi][ni][0] + b0, acc[mi][ni][1] + b1);
                __half2 h1 = __floats2half2_rn(acc[mi][ni][2] + b0, acc[mi][ni][3] + b1);
                *(__half2*)&C[(size_t)r0 * N + col]       = h0;
                *(__half2*)&C[(size_t)(r0 + 8) * N + col] = h1;
            } else {
                float* C = (float*)Cv + coff;
                *(float2*)&C[(size_t)r0 * N + col] =
                    make_float2(acc[mi][ni][0] + b0, acc[mi][ni][1] + b1);
                *(float2*)&C[(size_t)(r0 + 8) * N + col] =
                    make_float2(acc[mi][ni][2] + b0, acc[mi][ni][3] + b1);
            }
        }
    }
}

// ---------------------------------------------------------------------------
// SpMM gather core: 128 threads/row, 2 edge-parity groups of 64,
// 8 columns/thread via uint4 loads; deterministic grp0+grp1 combine.
// dinv scaling folded into staging (val * (dinv[i] * dinv[col])).
// ---------------------------------------------------------------------------
__device__ __forceinline__ int spmm_gather(
    const __half* __restrict__ Y, int i, int t,
    int* s_col, float* s_val, float* s_part, float* acc /*[8]*/)
{
    const int cnt  = g_cnt[i];
    const int base = i * MAXNZ;
    const float di = g_dinv[i];
    for (int k = t; k < cnt; k += 128) {
        const int c = g_colv[base + k];
        s_col[k] = c;
        s_val[k] = g_valv[base + k] * (di * g_dinv[c]);
    }
    __syncthreads();

    const int half_id = t >> 6;
    const int ht      = t & 63;
    const int h       = ht * 8;

    #pragma unroll
    for (int j = 0; j < 8; j++) acc[j] = 0.f;

    #pragma unroll 4
    for (int k = half_id; k < cnt; k += 2) {
        const uint4 y = *(const uint4*)&Y[(size_t)s_col[k] * HH + h];
        const float v = s_val[k];
        const float2 f0 = __half22float2(*(const __half2*)&y.x);
        const float2 f1 = __half22float2(*(const __half2*)&y.y);
        const float2 f2 = __half22float2(*(const __half2*)&y.z);
        const float2 f3 = __half22float2(*(const __half2*)&y.w);
        acc[0] += v * f0.x; acc[1] += v * f0.y;
        acc[2] += v * f1.x; acc[3] += v * f1.y;
        acc[4] += v * f2.x; acc[5] += v * f2.y;
        acc[6] += v * f3.x; acc[7] += v * f3.y;
    }

    if (half_id == 1) {
        #pragma unroll
        for (int j = 0; j < 8; j++) s_part[ht * 8 + j] = acc[j];
    }
    __syncthreads();
    if (half_id == 0) {
        #pragma unroll
        for (int j = 0; j < 8; j++) acc[j] += s_part[ht * 8 + j];
    }
    return h;
}

// ---------------------------------------------------------------------------
// SpMM -> fp16 out (layers 1-2 pre-GEMM)
// ---------------------------------------------------------------------------
__global__ __launch_bounds__(128) void spmm_kernel(
    const __half* __restrict__ Y, __half* __restrict__ out)
{
    __shared__ int   s_col[MAXNZ];
    __shared__ float s_val[MAXNZ];
    __shared__ float s_part[64 * 8];
    const int i = blockIdx.x;
    const int t = threadIdx.x;
    float acc[8];
    const int h = spmm_gather(Y, i, t, s_col, s_val, s_part, acc);

    if ((t >> 6) == 0) {
        __half2 o0 = __floats2half2_rn(acc[0], acc[1]);
        __half2 o1 = __floats2half2_rn(acc[2], acc[3]);
        __half2 o2 = __floats2half2_rn(acc[4], acc[5]);
        __half2 o3 = __floats2half2_rn(acc[6], acc[7]);
        uint4 o;
        o.x = *(uint32_t*)&o0;
        o.y = *(uint32_t*)&o1;
        o.z = *(uint32_t*)&o2;
        o.w = *(uint32_t*)&o3;
        *(uint4*)&out[(size_t)i * HH + h] = o;
    }
}

// ---------------------------------------------------------------------------
// SpMM + bias + LayerNorm + ReLU fused (layer 0), fp16 out
// ---------------------------------------------------------------------------
__global__ __launch_bounds__(128) void spmm_ln_kernel(
    const __half* __restrict__ Y, const float* __restrict__ bias,
    const float* __restrict__ g, const float* __restrict__ b,
    __half* __restrict__ out)
{
    __shared__ int   s_col[MAXNZ];
    __shared__ float s_val[MAXNZ];
    __shared__ float s_part[64 * 8];
    __shared__ float s_red[4];
    const int i = blockIdx.x;
    const int t = threadIdx.x;
    float acc[8];
    const int h = spmm_gather(Y, i, t, s_col, s_val, s_part, acc);

    const int half_id = t >> 6;
    const int ht      = t & 63;

    if (half_id == 0) {
        #pragma unroll
        for (int j = 0; j < 8; j++) acc[j] += bias[h + j];
        float lsum = 0.f;
        #pragma unroll
        for (int j = 0; j < 8; j++) lsum += acc[j];
        #pragma unroll
        for (int o = 16; o; o >>= 1) lsum += __shfl_xor_sync(0xffffffff, lsum, o);
        if ((ht & 31) == 0) s_red[ht >> 5] = lsum;
    }
    __syncthreads();
    if (half_id == 0) {
        const float mu = (s_red[0] + s_red[1]) * (1.f / HH);
        float lsq = 0.f;
        #pragma unroll
        for (int j = 0; j < 8; j++) {
            const float d = acc[j] - mu;
            lsq += d * d;
        }
        #pragma unroll
        for (int o = 16; o; o >>= 1) lsq += __shfl_xor_sync(0xffffffff, lsq, o);
        if ((ht & 31) == 0) s_red[2 + (ht >> 5)] = lsq;
    }
    __syncthreads();
    if (half_id == 0) {
        const float mu  = (s_red[0] + s_red[1]) * (1.f / HH);
        const float var = (s_red[2] + s_red[3]) * (1.f / HH);
        const float r = rsqrtf(var + LN_EPS);
        float o[8];
        #pragma unroll
        for (int j = 0; j < 8; j++)
            o[j] = fmaxf((acc[j] - mu) * r * g[h + j] + b[h + j], 0.f);
        __half2 h0 = __floats2half2_rn(o[0], o[1]);
        __half2 h1 = __floats2half2_rn(o[2], o[3]);
        __half2 h2 = __floats2half2_rn(o[4], o[5]);
        __half2 h3 = __floats2half2_rn(o[6], o[7]);
        uint4 ov;
        ov.x = *(uint32_t*)&h0;
        ov.y = *(uint32_t*)&h1;
        ov.z = *(uint32_t*)&h2;
        ov.w = *(uint32_t*)&h3;
        *(uint4*)&out[(size_t)i * HH + h] = ov;
    }
}

// ---------------------------------------------------------------------------
// LayerNorm + ReLU (fp16 in, fp16 out) — layers 1-2
// ---------------------------------------------------------------------------
__global__ __launch_bounds__(128) void ln_relu_kernel(
    const __half* __restrict__ Z, const float* __restrict__ g,
    const float* __restrict__ b, __half* __restrict__ out)
{
    const int i = blockIdx.x;
    const int t = threadIdx.x;
    __shared__ float s[4];

    const int h = t * 4;
    const uint2 zin = *(const uint2*)&Z[(size_t)i * HH + h];
    const float2 p0 = __half22float2(*(const __half2*)&zin.x);
    const float2 p1 = __half22float2(*(const __half2*)&zin.y);
    const float vx = p0.x, vy = p0.y, vz = p1.x, vw = p1.y;

    float lsum = vx + vy + vz + vw;
    #pragma unroll
    for (int o = 16; o; o >>= 1) lsum += __shfl_xor_sync(0xffffffff, lsum, o);
    if ((t & 31) == 0) s[t >> 5] = lsum;
    __syncthreads();
    const float mu = (s[0] + s[1] + s[2] + s[3]) * (1.f / HH);

    const float dx = vx - mu, dy = vy - mu, dz = vz - mu, dw = vw - mu;
    float lsq = dx * dx + dy * dy + dz * dz + dw * dw;
    #pragma unroll
    for (int o = 16; o; o >>= 1) lsq += __shfl_xor_sync(0xffffffff, lsq, o);
    __syncthreads();
    if ((t & 31) == 0) s[t >> 5] = lsq;
    __syncthreads();
    const float var = (s[0] + s[1] + s[2] + s[3]) * (1.f / HH);
    const float r = rsqrtf(var + LN_EPS);

    const float4 gg = *(const float4*)&g[h];
    const float4 bb = *(const float4*)&b[h];
    const float ox = fmaxf(dx * r * gg.x + bb.x, 0.f);
    const float oy = fmaxf(dy * r * gg.y + bb.y, 0.f);
    const float oz = fmaxf(dz * r * gg.z + bb.z, 0.f);
    const float ow = fmaxf(dw * r * gg.w + bb.w, 0.f);

    __half2 o0 = __floats2half2_rn(ox, oy);
    __half2 o1 = __floats2half2_rn(oz, ow);
    uint2 o;
    o.x = *(uint32_t*)&o0;
    o.y = *(uint32_t*)&o1;
    *(uint2*)&out[(size_t)i * HH + h] = o;
}

// ---------------------------------------------------------------------------
// Host launcher
// ---------------------------------------------------------------------------
extern "C" void kernel_launch(void* const* d_in, const int* in_sizes, int n_in,
                              void* d_out, int out_size)
{
    const float* node   = (const float*)d_in[0];
    const float* adj    = (const float*)d_in[1];
    const float* conv_w = (const float*)d_in[2];
    const float* conv_b = (const float*)d_in[3];
    const float* mlp_w  = (const float*)d_in[4];
    const float* mlp_b  = (const float*)d_in[5];
    const float* ln_g   = (const float*)d_in[6];
    const float* ln_b   = (const float*)d_in[7];
    const float* lin_w  = (const float*)d_in[8];
    const float* lin_b  = (const float*)d_in[9];
    float* out = (float*)d_out;

    __half *Xh, *Sh, *Zh, *Wmt, *Wch, *Wth;
    float *bf;
    cudaGetSymbolAddress((void**)&Xh,  g_Xh);
    cudaGetSymbolAddress((void**)&Sh,  g_Sh);
    cudaGetSymbolAddress((void**)&Zh,  g_Zh);
    cudaGetSymbolAddress((void**)&Wmt, g_Wmt);
    cudaGetSymbolAddress((void**)&Wch, g_Wch);
    cudaGetSymbolAddress((void**)&Wth, g_Wth);
    cudaGetSymbolAddress((void**)&bf,  g_bf);

    cudaFuncSetAttribute(hgemm_kernel<false>,
                         cudaFuncAttributeMaxDynamicSharedMemorySize, HSMEM_BYTES);
    cudaFuncSetAttribute(hgemm_kernel<true>,
                         cudaFuncAttributeMaxDynamicSharedMemorySize, HSMEM_BYTES);

    const bool multi = g_hx.ok;
    cudaStream_t sA = multi ? g_hx.s1 : (cudaStream_t)0;  // CSR chain
    cudaStream_t sB = multi ? g_hx.s2 : (cudaStream_t)0;  // weights + layer-0 GEMM

    if (multi) {
        cudaEventRecord(g_hx.e0, 0);
        cudaStreamWaitEvent(sA, g_hx.e0, 0);
        cudaStreamWaitEvent(sB, g_hx.e0, 0);
    }

    // Stream A: CSR build (DRAM-bound); dinv scaling folded into SpMM.
    build_csr_kernel<<<NN, 256, 0, sA>>>(adj);

    // Stream B: merged prep + fusion GEMM + bias + layer-0 GEMM
    const size_t WS = (size_t)HH * HH;
    prep_kernel<<<dim3(16, 16, 23), dim3(32, 32), 0, sB>>>(mlp_w, lin_w, conv_w, node);
    // W'^T[n][k] = sum_j Wmt[n][j] * Wch[k][j]  (batched, half out)
    hgemm_kernel<true><<<dim3(4, 4, LL), 256, HSMEM_BYTES, sB>>>(
        Wmt, Wch, nullptr, Wth, HH, HH, HH, WS, WS, WS);
    bias_fuse_kernel<<<dim3(HH / 16, LL), 256, 0, sB>>>(conv_b, mlp_w, mlp_b);
    // H0 = x @ W'_0  (propagation commutes: Â(xW') = (Âx)W')
    hgemm_kernel<true><<<dim3(HH / 128, NN / 128), 256, HSMEM_BYTES, sB>>>(
        Xh, Wth, nullptr, Sh, NN, HH, HH, 0, 0, 0);

    if (multi) {
        cudaEventRecord(g_hx.e1, sA);
        cudaEventRecord(g_hx.e2, sB);
        cudaStreamWaitEvent((cudaStream_t)0, g_hx.e1, 0);
        cudaStreamWaitEvent((cudaStream_t)0, g_hx.e2, 0);
    }

    // Layer 0: Xh = relu(LN( Â @ H0 + b'_0 ))
    spmm_ln_kernel<<<NN, 128>>>(Sh, bf, ln_g, ln_b, Xh);

    // Layers 1..2: Sh = Â @ Xh ; Zh = Sh @ W'_l + b'_l (fp16) ; Xh = relu(LN(Zh))
    const dim3 gdim(HH / 128, NN / 128);
    for (int l = 1; l < LL; l++) {
        spmm_kernel<<<NN, 128>>>(Xh, Sh);
        hgemm_kernel<true><<<gdim, 256, HSMEM_BYTES>>>(
            Sh, Wth + (size_t)l * WS, bf + (size_t)l * HH, Zh, NN, HH, HH, 0, 0, 0);
        ln_relu_kernel<<<NN, 128>>>(Zh, ln_g + (size_t)l * HH,
                                    ln_b + (size_t)l * HH, Xh);
    }
    // out = x3 @ lin_w + lin_b
    hgemm_kernel<false><<<dim3(OO / 128, NN / 128), 256, HSMEM_BYTES>>>(
        Xh, Wth + (size_t)3 * WS, lin_b, out, NN, HH, OO, 0, 0, 0);
}

// round 16
// speedup vs baseline: 1.0241x; 1.0241x over previous
#include <cuda_runtime.h>
#include <cuda_fp16.h>
#include <cstdint>

// Problem constants
#define NN 8192
#define HH 512
#define LL 3
#define OO 512
#define MAXNZ 256
#define LN_EPS 1e-5f

// fp16 GEMM tiling
#define HBK 64
#define HA_STRIDE 72
#define HA_BYTES (128 * HA_STRIDE * 2)
#define HSTAGE_BYTES (2 * HA_BYTES)
#define HSMEM_BYTES (2 * HSTAGE_BYTES)

// ---------------------------------------------------------------------------
// Scratch (device globals — no allocations allowed)
// ---------------------------------------------------------------------------
__device__ __half g_Xh[NN * HH];        // activations, fp16
__device__ __half g_Sh[NN * HH];        // fp16 intermediate (SpMM out / H0)
__device__ __half g_Zh[NN * HH];        // fp16 pre-LN (layers 1-2)
__device__ __half g_Wmt[LL * HH * HH];  // mlp_w transposed, half [n][j]
__device__ __half g_Wch[LL * HH * HH];  // conv_w as-is, half [k][j]
__device__ __half g_Wth[4 * HH * HH];   // W'^T (3) + lin_w^T (1), half [n][k]
__device__ float  g_bf[LL * HH];        // fused bias
__device__ int    g_colv[NN * MAXNZ];
__device__ float  g_valv[NN * MAXNZ];   // RAW adjacency weights (unscaled)
__device__ int    g_cnt[NN];
__device__ float  g_dinv[NN];

// ---------------------------------------------------------------------------
// Streams (module-load creation; serial fallback)
// ---------------------------------------------------------------------------
struct HxStreams {
    cudaStream_t s1 = nullptr, s2 = nullptr;
    cudaEvent_t  e0 = nullptr, e1 = nullptr, e2 = nullptr;
    bool ok = false;
    HxStreams() {
        ok = (cudaStreamCreateWithFlags(&s1, cudaStreamNonBlocking) == cudaSuccess) &&
             (cudaStreamCreateWithFlags(&s2, cudaStreamNonBlocking) == cudaSuccess) &&
             (cudaEventCreateWithFlags(&e0, cudaEventDisableTiming) == cudaSuccess) &&
             (cudaEventCreateWithFlags(&e1, cudaEventDisableTiming) == cudaSuccess) &&
             (cudaEventCreateWithFlags(&e2, cudaEventDisableTiming) == cudaSuccess);
    }
};
static HxStreams g_hx;

// ---------------------------------------------------------------------------
// Helpers
// ---------------------------------------------------------------------------
__device__ __forceinline__ void cp16(uint32_t smaddr, const void* gptr) {
    asm volatile("cp.async.cg.shared.global [%0], [%1], 16;" :: "r"(smaddr), "l"(gptr));
}
__device__ __forceinline__ void cp_commit() {
    asm volatile("cp.async.commit_group;");
}
template<int N_> __device__ __forceinline__ void cp_wait() {
    asm volatile("cp.async.wait_group %0;" :: "n"(N_));
}
__device__ __forceinline__ void ldsm_x4(uint32_t* r, uint32_t addr) {
    asm volatile("ldmatrix.sync.aligned.m8n8.x4.shared.b16 {%0,%1,%2,%3}, [%4];"
                 : "=r"(r[0]), "=r"(r[1]), "=r"(r[2]), "=r"(r[3]) : "r"(addr));
}

// ---------------------------------------------------------------------------
// dense adjacency -> CSR (raw weights) + dinv (deterministic order)
// ---------------------------------------------------------------------------
__global__ __launch_bounds__(256) void build_csr_kernel(const float* __restrict__ Aadj)
{
    const int i = blockIdx.x;
    const int t = threadIdx.x;

    __shared__ float s_red[256];
    __shared__ int   s_scan[256];
    __shared__ int   s_diag;
    if (t == 0) s_diag = 0;
    __syncthreads();

    const float* row = Aadj + (size_t)i * NN;
    const int j0 = t * 32;

    float lsum = 0.f;
    int   lcnt = 0;
    #pragma unroll
    for (int q = 0; q < 8; q++) {
        const float4 a = *(const float4*)&row[j0 + q * 4];
        const float vv[4] = {a.x, a.y, a.z, a.w};
        #pragma unroll
        for (int e = 0; e < 4; e++) {
            const int j = j0 + q * 4 + e;
            const float v = vv[e];
            if (v > 0.f) {
                lsum += v;
                lcnt++;
                if (j == i) s_diag = 1;
            }
        }
    }

    s_scan[t] = lcnt;
    s_red[t]  = lsum;
    __syncthreads();

    for (int st = 128; st > 0; st >>= 1) {
        if (t < st) s_red[t] += s_red[t + st];
        __syncthreads();
    }
    for (int st = 1; st < 256; st <<= 1) {
        int add = (t >= st) ? s_scan[t - st] : 0;
        __syncthreads();
        s_scan[t] += add;
        __syncthreads();
    }

    const int excl  = s_scan[t] - lcnt;
    const int total = s_scan[255];
    const int selfloop = (s_diag == 0);

    int off = excl;
    const int base = i * MAXNZ;
    #pragma unroll
    for (int q = 0; q < 8; q++) {
        const float4 a = *(const float4*)&row[j0 + q * 4];
        const float vv[4] = {a.x, a.y, a.z, a.w};
        #pragma unroll
        for (int e = 0; e < 4; e++) {
            const int j = j0 + q * 4 + e;
            const float v = vv[e];
            if (v > 0.f) {
                if (off < MAXNZ) {
                    g_colv[base + off] = j;
                    g_valv[base + off] = v;
                }
                off++;
            }
        }
    }

    if (t == 0) {
        int   c   = total;
        float deg = s_red[0];
        if (selfloop) {
            if (c < MAXNZ) {
                g_colv[base + c] = i;
                g_valv[base + c] = 1.f;
            }
            c++;
            deg += 1.f;
        }
        g_cnt[i]  = c < MAXNZ ? c : MAXNZ;
        g_dinv[i] = (deg > 0.f) ? rsqrtf(deg) : 0.f;
    }
}

// ---------------------------------------------------------------------------
// fp32 -> fp16 elementwise (node features)
// ---------------------------------------------------------------------------
__global__ __launch_bounds__(256) void f2h_kernel(const float* __restrict__ in,
                                                  __half* __restrict__ out)
{
    const int i = (blockIdx.x * 256 + threadIdx.x) * 4;
    const float4 v = *(const float4*)&in[i];
    __half2 h0 = __floats2half2_rn(v.x, v.y);
    __half2 h1 = __floats2half2_rn(v.z, v.w);
    uint2 o;
    o.x = *(uint32_t*)&h0;
    o.y = *(uint32_t*)&h1;
    *(uint2*)&out[i] = o;
}

// ---------------------------------------------------------------------------
// Merged weight prep (one launch): grid (16,16,7), block (32,32)
//   z 0..2 : transpose mlp_w[z] fp32 [k][n] -> fp16 g_Wmt[z] [n][k]
//   z 3    : transpose lin_w    fp32 [k][n] -> fp16 g_Wth slot 3 [n][k]
//   z 4..6 : f2h conv_w[z-4] -> g_Wch[z-4] (as-is layout)
// ---------------------------------------------------------------------------
__global__ __launch_bounds__(1024) void prep_weights_kernel(
    const float* __restrict__ mlp_w, const float* __restrict__ lin_w,
    const float* __restrict__ conv_w)
{
    const int z = blockIdx.z;
    if (z < 4) {
        __shared__ float ts[32][33];
        const float* in = (z < 3) ? (mlp_w + (size_t)z * HH * HH) : lin_w;
        __half* out = (z < 3) ? (g_Wmt + (size_t)z * HH * HH)
                              : (g_Wth + (size_t)3 * HH * HH);
        const int k_in = blockIdx.y * 32 + threadIdx.y;
        const int n_in = blockIdx.x * 32 + threadIdx.x;
        ts[threadIdx.y][threadIdx.x] = in[(size_t)k_in * HH + n_in];
        __syncthreads();
        const int n_out = blockIdx.x * 32 + threadIdx.y;
        const int k_out = blockIdx.y * 32 + threadIdx.x;
        out[(size_t)n_out * HH + k_out] = __float2half_rn(ts[threadIdx.x][threadIdx.y]);
    } else {
        const int m = z - 4;
        const int tile = blockIdx.y * 16 + blockIdx.x;           // 0..255
        const size_t off = (size_t)m * HH * HH
                         + (size_t)tile * 1024 + threadIdx.y * 32 + threadIdx.x;
        g_Wch[off] = __float2half_rn(conv_w[off]);
    }
}

// ---------------------------------------------------------------------------
// Fused bias (coalesced): bf[l][n] = conv_b[l] @ mlp_w[l] + mlp_b[l]
// Reads the already-transposed fp16 Wmt[n][j] — unit-stride 1KB per warp.
// grid (HH/8, LL) = (64, 3), 256 thr = 8 warps, one output n per warp.
// Deterministic: per-lane fixed-order partials + shfl tree reduce.
// (With conv_b == 0 the result is exactly mlp_b regardless of rounding.)
// ---------------------------------------------------------------------------
__global__ __launch_bounds__(256) void bias_fuse_kernel(
    const float* __restrict__ conv_b, const float* __restrict__ mlp_b)
{
    __shared__ float s_cb[HH];
    const int l    = blockIdx.y;
    const int warp = threadIdx.x >> 5;
    const int lane = threadIdx.x & 31;
    const int n    = blockIdx.x * 8 + warp;

    for (int j = threadIdx.x; j < HH; j += 256)
        s_cb[j] = conv_b[l * HH + j];
    __syncthreads();

    const __half* Wrow = g_Wmt + (size_t)l * HH * HH + (size_t)n * HH;
    float acc = 0.f;
    // lane handles j = lane*16 .. lane*16+15 (two uint4 = 16 halves), fixed order
    const int j0 = lane * 16;
    #pragma unroll
    for (int q = 0; q < 2; q++) {
        const uint4 w = *(const uint4*)&Wrow[j0 + q * 8];
        const float2 a0 = __half22float2(*(const __half2*)&w.x);
        const float2 a1 = __half22float2(*(const __half2*)&w.y);
        const float2 a2 = __half22float2(*(const __half2*)&w.z);
        const float2 a3 = __half22float2(*(const __half2*)&w.w);
        const int jb = j0 + q * 8;
        acc += s_cb[jb]     * a0.x; acc += s_cb[jb + 1] * a0.y;
        acc += s_cb[jb + 2] * a1.x; acc += s_cb[jb + 3] * a1.y;
        acc += s_cb[jb + 4] * a2.x; acc += s_cb[jb + 5] * a2.y;
        acc += s_cb[jb + 6] * a3.x; acc += s_cb[jb + 7] * a3.y;
    }
    #pragma unroll
    for (int o = 16; o; o >>= 1) acc += __shfl_xor_sync(0xffffffff, acc, o);
    if (lane == 0)
        g_bf[l * HH + n] = acc + mlp_b[l * HH + n];
}

// ---------------------------------------------------------------------------
// fp16 tensor-core GEMM  C[M,N] = A[M,K] @ Bt[N,K]^T (+ bias), fp32 accum.
// OUT_HALF: write __half (bias still added if non-null). Batched over z.
// ---------------------------------------------------------------------------
template<bool OUT_HALF>
__global__ __launch_bounds__(256, 2) void hgemm_kernel(
    const __half* __restrict__ A, const __half* __restrict__ Bt,
    const float* __restrict__ bias, void* __restrict__ Cv,
    int M, int K, int N, size_t sa, size_t sb, size_t sc)
{
    extern __shared__ char smh[];
    const uint32_t smbase = (uint32_t)__cvta_generic_to_shared(smh);

    A  += (size_t)blockIdx.z * sa;
    Bt += (size_t)blockIdx.z * sb;
    const size_t coff = (size_t)blockIdx.z * sc;

    const int t    = threadIdx.x;
    const int warp = t >> 5;
    const int lane = t & 31;
    const int g    = lane >> 2;
    const int tg   = lane & 3;
    const int wm   = warp >> 2;
    const int wn   = warp & 3;
    const int m0   = blockIdx.y * 128;
    const int n0   = blockIdx.x * 128;

    const int sel = lane >> 3;
    const int lr  = lane & 7;
    const int arow  = lr + ((sel & 1) ? 8 : 0);
    const int akoff = (sel & 2) ? 8 : 0;
    const int brow  = lr + ((sel & 2) ? 8 : 0);
    const int bkoff = (sel & 1) ? 8 : 0;

    float acc[4][4][4];
    #pragma unroll
    for (int a = 0; a < 4; a++)
        #pragma unroll
        for (int b = 0; b < 4; b++)
            #pragma unroll
            for (int c = 0; c < 4; c++) acc[a][b][c] = 0.f;

    const int NT = K / HBK;

    auto load_stage = [&](int s, int k0) {
        const uint32_t sb_ = smbase + (uint32_t)s * HSTAGE_BYTES;
        #pragma unroll
        for (int i = 0; i < 4; i++) {
            const int id = t + i * 256;
            const int r  = id >> 3;
            const int c  = id & 7;
            const uint32_t so = (uint32_t)(r * (HA_STRIDE * 2) + c * 16);
            cp16(sb_ + so,            &A [(size_t)(m0 + r) * K + k0 + c * 8]);
            cp16(sb_ + HA_BYTES + so, &Bt[(size_t)(n0 + r) * K + k0 + c * 8]);
        }
    };

    load_stage(0, 0);
    cp_commit();

    for (int it = 0; it < NT; it++) {
        const int cur = it & 1;
        if (it + 1 < NT) {
            load_stage((it + 1) & 1, (it + 1) * HBK);
            cp_commit();
            cp_wait<1>();
        } else {
            cp_wait<0>();
        }
        __syncthreads();

        const uint32_t sA = smbase + (uint32_t)cur * HSTAGE_BYTES;
        const uint32_t sB = sA + HA_BYTES;

        #pragma unroll
        for (int ks = 0; ks < HBK; ks += 16) {
            uint32_t af[4][4];
            #pragma unroll
            for (int mi = 0; mi < 4; mi++) {
                const int r = wm * 64 + mi * 16 + arow;
                ldsm_x4(af[mi], sA + (uint32_t)(r * (HA_STRIDE * 2) + (ks + akoff) * 2));
            }
            uint32_t bfr[2][4];
            #pragma unroll
            for (int p = 0; p < 2; p++) {
                const int r = wn * 32 + p * 16 + brow;
                ldsm_x4(bfr[p], sB + (uint32_t)(r * (HA_STRIDE * 2) + (ks + bkoff) * 2));
            }
            #pragma unroll
            for (int mi = 0; mi < 4; mi++)
                #pragma unroll
                for (int ni = 0; ni < 4; ni++) {
                    const int p   = ni >> 1;
                    const int idx = (ni & 1) * 2;
                    asm volatile(
                        "mma.sync.aligned.m16n8k16.row.col.f32.f16.f16.f32 "
                        "{%0,%1,%2,%3}, {%4,%5,%6,%7}, {%8,%9}, {%0,%1,%2,%3};"
                        : "+f"(acc[mi][ni][0]), "+f"(acc[mi][ni][1]),
                          "+f"(acc[mi][ni][2]), "+f"(acc[mi][ni][3])
                        : "r"(af[mi][0]), "r"(af[mi][1]),
                          "r"(af[mi][2]), "r"(af[mi][3]),
                          "r"(bfr[p][idx]), "r"(bfr[p][idx + 1]));
                }
        }
        __syncthreads();
    }

    #pragma unroll
    for (int ni = 0; ni < 4; ni++) {
        const int col = n0 + wn * 32 + ni * 8 + 2 * tg;
        float b0 = 0.f, b1 = 0.f;
        if (bias) { b0 = bias[col]; b1 = bias[col + 1]; }
        #pragma unroll
        for (int mi = 0; mi < 4; mi++) {
            const int r0 = m0 + wm * 64 + mi * 16 + g;
            if (OUT_HALF) {
                __half* C = (__half*)Cv + coff;
                __half2 h0 = __floats2half2_rn(acc[mi][ni][0] + b0, acc[mi][ni][1] + b1);
                __half2 h1 = __floats2half2_rn(acc[mi][ni][2] + b0, acc[mi][ni][3] + b1);
                *(__half2*)&C[(size_t)r0 * N + col]       = h0;
                *(__half2*)&C[(size_t)(r0 + 8) * N + col] = h1;
            } else {
                float* C = (float*)Cv + coff;
                *(float2*)&C[(size_t)r0 * N + col] =
                    make_float2(acc[mi][ni][0] + b0, acc[mi][ni][1] + b1);
                *(float2*)&C[(size_t)(r0 + 8) * N + col] =
                    make_float2(acc[mi][ni][2] + b0, acc[mi][ni][3] + b1);
            }
        }
    }
}

// ---------------------------------------------------------------------------
// SpMM gather core: 128 threads/row, 2 edge-parity groups of 64,
// 8 columns/thread via uint4 loads; deterministic grp0+grp1 combine.
// dinv scaling folded into staging (val * (dinv[i] * dinv[col])).
// ---------------------------------------------------------------------------
__device__ __forceinline__ int spmm_gather(
    const __half* __restrict__ Y, int i, int t,
    int* s_col, float* s_val, float* s_part, float* acc /*[8]*/)
{
    const int cnt  = g_cnt[i];
    const int base = i * MAXNZ;
    const float di = g_dinv[i];
    for (int k = t; k < cnt; k += 128) {
        const int c = g_colv[base + k];
        s_col[k] = c;
        s_val[k] = g_valv[base + k] * (di * g_dinv[c]);
    }
    __syncthreads();

    const int half_id = t >> 6;
    const int ht      = t & 63;
    const int h       = ht * 8;

    #pragma unroll
    for (int j = 0; j < 8; j++) acc[j] = 0.f;

    #pragma unroll 4
    for (int k = half_id; k < cnt; k += 2) {
        const uint4 y = *(const uint4*)&Y[(size_t)s_col[k] * HH + h];
        const float v = s_val[k];
        const float2 f0 = __half22float2(*(const __half2*)&y.x);
        const float2 f1 = __half22float2(*(const __half2*)&y.y);
        const float2 f2 = __half22float2(*(const __half2*)&y.z);
        const float2 f3 = __half22float2(*(const __half2*)&y.w);
        acc[0] += v * f0.x; acc[1] += v * f0.y;
        acc[2] += v * f1.x; acc[3] += v * f1.y;
        acc[4] += v * f2.x; acc[5] += v * f2.y;
        acc[6] += v * f3.x; acc[7] += v * f3.y;
    }

    if (half_id == 1) {
        #pragma unroll
        for (int j = 0; j < 8; j++) s_part[ht * 8 + j] = acc[j];
    }
    __syncthreads();
    if (half_id == 0) {
        #pragma unroll
        for (int j = 0; j < 8; j++) acc[j] += s_part[ht * 8 + j];
    }
    return h;
}

// ---------------------------------------------------------------------------
// SpMM -> fp16 out (layers 1-2 pre-GEMM)
// ---------------------------------------------------------------------------
__global__ __launch_bounds__(128) void spmm_kernel(
    const __half* __restrict__ Y, __half* __restrict__ out)
{
    __shared__ int   s_col[MAXNZ];
    __shared__ float s_val[MAXNZ];
    __shared__ float s_part[64 * 8];
    const int i = blockIdx.x;
    const int t = threadIdx.x;
    float acc[8];
    const int h = spmm_gather(Y, i, t, s_col, s_val, s_part, acc);

    if ((t >> 6) == 0) {
        __half2 o0 = __floats2half2_rn(acc[0], acc[1]);
        __half2 o1 = __floats2half2_rn(acc[2], acc[3]);
        __half2 o2 = __floats2half2_rn(acc[4], acc[5]);
        __half2 o3 = __floats2half2_rn(acc[6], acc[7]);
        uint4 o;
        o.x = *(uint32_t*)&o0;
        o.y = *(uint32_t*)&o1;
        o.z = *(uint32_t*)&o2;
        o.w = *(uint32_t*)&o3;
        *(uint4*)&out[(size_t)i * HH + h] = o;
    }
}

// ---------------------------------------------------------------------------
// SpMM + bias + LayerNorm + ReLU fused (layer 0), fp16 out
// ---------------------------------------------------------------------------
__global__ __launch_bounds__(128) void spmm_ln_kernel(
    const __half* __restrict__ Y, const float* __restrict__ bias,
    const float* __restrict__ g, const float* __restrict__ b,
    __half* __restrict__ out)
{
    __shared__ int   s_col[MAXNZ];
    __shared__ float s_val[MAXNZ];
    __shared__ float s_part[64 * 8];
    __shared__ float s_red[4];
    const int i = blockIdx.x;
    const int t = threadIdx.x;
    float acc[8];
    const int h = spmm_gather(Y, i, t, s_col, s_val, s_part, acc);

    const int half_id = t >> 6;
    const int ht      = t & 63;

    if (half_id == 0) {
        #pragma unroll
        for (int j = 0; j < 8; j++) acc[j] += bias[h + j];
        float lsum = 0.f;
        #pragma unroll
        for (int j = 0; j < 8; j++) lsum += acc[j];
        #pragma unroll
        for (int o = 16; o; o >>= 1) lsum += __shfl_xor_sync(0xffffffff, lsum, o);
        if ((ht & 31) == 0) s_red[ht >> 5] = lsum;
    }
    __syncthreads();
    if (half_id == 0) {
        const float mu = (s_red[0] + s_red[1]) * (1.f / HH);
        float lsq = 0.f;
        #pragma unroll
        for (int j = 0; j < 8; j++) {
            const float d = acc[j] - mu;
            lsq += d * d;
        }
        #pragma unroll
        for (int o = 16; o; o >>= 1) lsq += __shfl_xor_sync(0xffffffff, lsq, o);
        if ((ht & 31) == 0) s_red[2 + (ht >> 5)] = lsq;
    }
    __syncthreads();
    if (half_id == 0) {
        const float mu  = (s_red[0] + s_red[1]) * (1.f / HH);
        const float var = (s_red[2] + s_red[3]) * (1.f / HH);
        const float r = rsqrtf(var + LN_EPS);
        float o[8];
        #pragma unroll
        for (int j = 0; j < 8; j++)
            o[j] = fmaxf((acc[j] - mu) * r * g[h + j] + b[h + j], 0.f);
        __half2 h0 = __floats2half2_rn(o[0], o[1]);
        __half2 h1 = __floats2half2_rn(o[2], o[3]);
        __half2 h2 = __floats2half2_rn(o[4], o[5]);
        __half2 h3 = __floats2half2_rn(o[6], o[7]);
        uint4 ov;
        ov.x = *(uint32_t*)&h0;
        ov.y = *(uint32_t*)&h1;
        ov.z = *(uint32_t*)&h2;
        ov.w = *(uint32_t*)&h3;
        *(uint4*)&out[(size_t)i * HH + h] = ov;
    }
}

// ---------------------------------------------------------------------------
// LayerNorm + ReLU (fp16 in, fp16 out) — layers 1-2
// ---------------------------------------------------------------------------
__global__ __launch_bounds__(128) void ln_relu_kernel(
    const __half* __restrict__ Z, const float* __restrict__ g,
    const float* __restrict__ b, __half* __restrict__ out)
{
    const int i = blockIdx.x;
    const int t = threadIdx.x;
    __shared__ float s[4];

    const int h = t * 4;
    const uint2 zin = *(const uint2*)&Z[(size_t)i * HH + h];
    const float2 p0 = __half22float2(*(const __half2*)&zin.x);
    const float2 p1 = __half22float2(*(const __half2*)&zin.y);
    const float vx = p0.x, vy = p0.y, vz = p1.x, vw = p1.y;

    float lsum = vx + vy + vz + vw;
    #pragma unroll
    for (int o = 16; o; o >>= 1) lsum += __shfl_xor_sync(0xffffffff, lsum, o);
    if ((t & 31) == 0) s[t >> 5] = lsum;
    __syncthreads();
    const float mu = (s[0] + s[1] + s[2] + s[3]) * (1.f / HH);

    const float dx = vx - mu, dy = vy - mu, dz = vz - mu, dw = vw - mu;
    float lsq = dx * dx + dy * dy + dz * dz + dw * dw;
    #pragma unroll
    for (int o = 16; o; o >>= 1) lsq += __shfl_xor_sync(0xffffffff, lsq, o);
    __syncthreads();
    if ((t & 31) == 0) s[t >> 5] = lsq;
    __syncthreads();
    const float var = (s[0] + s[1] + s[2] + s[3]) * (1.f / HH);
    const float r = rsqrtf(var + LN_EPS);

    const float4 gg = *(const float4*)&g[h];
    const float4 bb = *(const float4*)&b[h];
    const float ox = fmaxf(dx * r * gg.x + bb.x, 0.f);
    const float oy = fmaxf(dy * r * gg.y + bb.y, 0.f);
    const float oz = fmaxf(dz * r * gg.z + bb.z, 0.f);
    const float ow = fmaxf(dw * r * gg.w + bb.w, 0.f);

    __half2 o0 = __floats2half2_rn(ox, oy);
    __half2 o1 = __floats2half2_rn(oz, ow);
    uint2 o;
    o.x = *(uint32_t*)&o0;
    o.y = *(uint32_t*)&o1;
    *(uint2*)&out[(size_t)i * HH + h] = o;
}

// ---------------------------------------------------------------------------
// Host launcher
// ---------------------------------------------------------------------------
extern "C" void kernel_launch(void* const* d_in, const int* in_sizes, int n_in,
                              void* d_out, int out_size)
{
    const float* node   = (const float*)d_in[0];
    const float* adj    = (const float*)d_in[1];
    const float* conv_w = (const float*)d_in[2];
    const float* conv_b = (const float*)d_in[3];
    const float* mlp_w  = (const float*)d_in[4];
    const float* mlp_b  = (const float*)d_in[5];
    const float* ln_g   = (const float*)d_in[6];
    const float* ln_b   = (const float*)d_in[7];
    const float* lin_w  = (const float*)d_in[8];
    const float* lin_b  = (const float*)d_in[9];
    float* out = (float*)d_out;

    __half *Xh, *Sh, *Zh, *Wmt, *Wch, *Wth;
    float *bf;
    cudaGetSymbolAddress((void**)&Xh,  g_Xh);
    cudaGetSymbolAddress((void**)&Sh,  g_Sh);
    cudaGetSymbolAddress((void**)&Zh,  g_Zh);
    cudaGetSymbolAddress((void**)&Wmt, g_Wmt);
    cudaGetSymbolAddress((void**)&Wch, g_Wch);
    cudaGetSymbolAddress((void**)&Wth, g_Wth);
    cudaGetSymbolAddress((void**)&bf,  g_bf);

    cudaFuncSetAttribute(hgemm_kernel<false>,
                         cudaFuncAttributeMaxDynamicSharedMemorySize, HSMEM_BYTES);
    cudaFuncSetAttribute(hgemm_kernel<true>,
                         cudaFuncAttributeMaxDynamicSharedMemorySize, HSMEM_BYTES);

    const bool multi = g_hx.ok;
    cudaStream_t sA = multi ? g_hx.s1 : (cudaStream_t)0;  // CSR chain
    cudaStream_t sB = multi ? g_hx.s2 : (cudaStream_t)0;  // weights + layer-0 GEMM

    if (multi) {
        cudaEventRecord(g_hx.e0, 0);
        cudaStreamWaitEvent(sA, g_hx.e0, 0);
        cudaStreamWaitEvent(sB, g_hx.e0, 0);
    }

    // Stream A: CSR build (DRAM-bound); dinv scaling folded into SpMM.
    build_csr_kernel<<<NN, 256, 0, sA>>>(adj);

    // Stream B: weight prep + fusion GEMM + bias (from Wmt) + node f2h + layer-0 GEMM
    const size_t WS = (size_t)HH * HH;
    prep_weights_kernel<<<dim3(16, 16, 7), dim3(32, 32), 0, sB>>>(mlp_w, lin_w, conv_w);
    // W'^T[n][k] = sum_j Wmt[n][j] * Wch[k][j]  (batched, half out)
    hgemm_kernel<true><<<dim3(4, 4, LL), 256, HSMEM_BYTES, sB>>>(
        Wmt, Wch, nullptr, Wth, HH, HH, HH, WS, WS, WS);
    bias_fuse_kernel<<<dim3(HH / 8, LL), 256, 0, sB>>>(conv_b, mlp_b);
    f2h_kernel<<<(NN * HH) / 1024, 256, 0, sB>>>(node, Xh);
    // H0 = x @ W'_0  (propagation commutes: Â(xW') = (Âx)W')
    hgemm_kernel<true><<<dim3(HH / 128, NN / 128), 256, HSMEM_BYTES, sB>>>(
        Xh, Wth, nullptr, Sh, NN, HH, HH, 0, 0, 0);

    if (multi) {
        cudaEventRecord(g_hx.e1, sA);
        cudaEventRecord(g_hx.e2, sB);
        cudaStreamWaitEvent((cudaStream_t)0, g_hx.e1, 0);
        cudaStreamWaitEvent((cudaStream_t)0, g_hx.e2, 0);
    }

    // Layer 0: Xh = relu(LN( Â @ H0 + b'_0 ))
    spmm_ln_kernel<<<NN, 128>>>(Sh, bf, ln_g, ln_b, Xh);

    // Layers 1..2: Sh = Â @ Xh ; Zh = Sh @ W'_l + b'_l (fp16) ; Xh = relu(LN(Zh))
    const dim3 gdim(HH / 128, NN / 128);
    for (int l = 1; l < LL; l++) {
        spmm_kernel<<<NN, 128>>>(Xh, Sh);
        hgemm_kernel<true><<<gdim, 256, HSMEM_BYTES>>>(
            Sh, Wth + (size_t)l * WS, bf + (size_t)l * HH, Zh, NN, HH, HH, 0, 0, 0);
        ln_relu_kernel<<<NN, 128>>>(Zh, ln_g + (size_t)l * HH,
                                    ln_b + (size_t)l * HH, Xh);
    }
    // out = x3 @ lin_w + lin_b
    hgemm_kernel<false><<<dim3(OO / 128, NN / 128), 256, HSMEM_BYTES>>>(
        Xh, Wth + (size_t)3 * WS, lin_b, out, NN, HH, OO, 0, 0, 0);
}